// round 1
// baseline (speedup 1.0000x reference)
#include <cuda_runtime.h>
#include <math.h>

#define ISZ 256
#define NV  512
#define NF  1024
#define NEARP 0.1f
#define FARP  100.0f

// Per-face precomputed data (scratch via __device__ globals; no allocs).
__device__ float4 g_bbox[NF];   // xmin, xmax, ymin, ymax (inverted if invalid)
__device__ float4 g_p0[NF];     // x2, y2, a01=(y1-y2)/d, a02=(x2-x1)/d
__device__ float4 g_p1[NF];     // a11=(y2-y0)/d, a12=(x0-x2)/d, 1/z0, 1/z1
__device__ float  g_rz2[NF];    // 1/z2
__device__ float  g_partial[256];

struct Cam {
    float ex, ey, ez;
    float r00, r01, r02, r10, r11, r12, r20, r21, r22;
    float width;
};

// ---------------------------------------------------------------------------
// Kernel 1: transform vertices + build per-face edge/bbox data. 1 block.
// ---------------------------------------------------------------------------
__global__ void prep_kernel(const float* __restrict__ verts,
                            const int*   __restrict__ faces,
                            Cam cam)
{
    __shared__ float sx[NV], sy[NV], sz[NV];
    int t = threadIdx.x;

    if (t < NV) {
        float vx = verts[3*t+0] - cam.ex;
        float vy = verts[3*t+1] - cam.ey;
        float vz = verts[3*t+2] - cam.ez;
        // (v-eye) @ R.T  (rows of R are x,y,z camera axes)
        float cx = vx*cam.r00 + vy*cam.r01 + vz*cam.r02;
        float cy = vx*cam.r10 + vy*cam.r11 + vz*cam.r12;
        float cz = vx*cam.r20 + vy*cam.r21 + vz*cam.r22;
        float zw = cz * cam.width;
        sx[t] = cx / zw;
        sy[t] = cy / zw;
        sz[t] = cz;
    }
    __syncthreads();

    int f = t;                      // blockDim.x == NF == 1024
    int i0 = faces[3*f+0], i1 = faces[3*f+1], i2 = faces[3*f+2];
    float x0 = sx[i0], x1 = sx[i1], x2 = sx[i2];
    float y0 = sy[i0], y1 = sy[i1], y2 = sy[i2];
    float z0 = sz[i0], z1 = sz[i1], z2 = sz[i2];

    float denom = (y1 - y2) * (x0 - x2) + (x2 - x1) * (y0 - y2);
    bool  valid = fabsf(denom) > 1e-9f;
    float rd = valid ? (1.0f / denom) : 1.0f;

    float4 bb;
    if (valid) {
        bb.x = fminf(x0, fminf(x1, x2));
        bb.y = fmaxf(x0, fmaxf(x1, x2));
        bb.z = fminf(y0, fminf(y1, y2));
        bb.w = fmaxf(y0, fmaxf(y1, y2));
    } else {
        bb.x = 1e30f; bb.y = -1e30f; bb.z = 1e30f; bb.w = -1e30f;
    }
    g_bbox[f] = bb;
    g_p0[f]   = make_float4(x2, y2, (y1 - y2) * rd, (x2 - x1) * rd);
    g_p1[f]   = make_float4((y2 - y0) * rd, (x0 - x2) * rd, 1.0f / z0, 1.0f / z1);
    g_rz2[f]  = 1.0f / z2;
}

// ---------------------------------------------------------------------------
// Kernel 2: rasterize one 16x16 tile per block with tile-level face culling,
// warp-cooperative early exit, and fixed-order block reduction of the loss.
// ---------------------------------------------------------------------------
__global__ __launch_bounds__(256) void raster_kernel(const float* __restrict__ ref)
{
    __shared__ int   s_list[NF];
    __shared__ int   s_cnt;
    __shared__ float s_red[256];

    int t  = threadIdx.x;
    int tx = blockIdx.x & 15;    // tile col
    int ty = blockIdx.x >> 4;    // tile row
    if (t == 0) s_cnt = 0;
    __syncthreads();

    // Tile bounds in NDC. xs = (2c+1-256)/256 increasing with c.
    // ys = (2*(255-r)+1-256)/256 decreasing with r.
    float txmin = (2.0f * (16 * tx)        + 1.0f - 256.0f) * (1.0f / 256.0f);
    float txmax = (2.0f * (16 * tx + 15)   + 1.0f - 256.0f) * (1.0f / 256.0f);
    float tymax = (2.0f * (255 - 16 * ty)        + 1.0f - 256.0f) * (1.0f / 256.0f);
    float tymin = (2.0f * (255 - (16 * ty + 15)) + 1.0f - 256.0f) * (1.0f / 256.0f);

    // Phase 1: cull faces against tile bbox.
    for (int f = t; f < NF; f += 256) {
        float4 bb = g_bbox[f];
        if (bb.x <= txmax && bb.y >= txmin && bb.z <= tymax && bb.w >= tymin) {
            int pos = atomicAdd(&s_cnt, 1);
            s_list[pos] = f;
        }
    }
    __syncthreads();
    int n = s_cnt;

    // Phase 2: per-pixel coverage with warp early exit.
    int c = 16 * tx + (t & 15);
    int r = 16 * ty + (t >> 4);
    float xs = (2.0f * c + 1.0f - 256.0f) * (1.0f / 256.0f);
    float ys = (2.0f * (255 - r) + 1.0f - 256.0f) * (1.0f / 256.0f);

    bool covered = false;
    for (int j = 0; j < n; j++) {
        if (!covered) {
            int f = s_list[j];
            float4 bb = g_bbox[f];
            if (xs >= bb.x && xs <= bb.y && ys >= bb.z && ys <= bb.w) {
                float4 p0 = g_p0[f];
                float dx = xs - p0.x, dy = ys - p0.y;
                float w0 = p0.z * dx + p0.w * dy;
                if (w0 > 0.0f) {
                    float4 p1 = g_p1[f];
                    float w1 = p1.x * dx + p1.y * dy;
                    float w2 = 1.0f - w0 - w1;
                    if (w1 > 0.0f && w2 > 0.0f) {
                        float inv_z = w0 * p1.z + w1 * p1.w + w2 * g_rz2[f];
                        float zp = 1.0f / inv_z;
                        if (zp > NEARP && zp < FARP) covered = true;
                    }
                }
            }
        }
        if (__all_sync(0xffffffffu, covered)) break;
    }

    // Phase 3: loss contribution + deterministic tree reduction.
    float s = covered ? 1.0f : 0.0f;
    float d = s - ref[r * ISZ + c];
    s_red[t] = d * d;
    __syncthreads();
    #pragma unroll
    for (int off = 128; off > 0; off >>= 1) {
        if (t < off) s_red[t] += s_red[t + off];
        __syncthreads();
    }
    if (t == 0) g_partial[blockIdx.x] = s_red[0];
}

// ---------------------------------------------------------------------------
// Kernel 3: final deterministic reduce of 256 partials.
// ---------------------------------------------------------------------------
__global__ void final_reduce(float* out)
{
    __shared__ float s[256];
    int t = threadIdx.x;
    s[t] = g_partial[t];
    __syncthreads();
    #pragma unroll
    for (int off = 128; off > 0; off >>= 1) {
        if (t < off) s[t] += s[t + off];
        __syncthreads();
    }
    if (t == 0) out[0] = s[0];
}

// ---------------------------------------------------------------------------
// Host: camera constants mirroring the reference fp32 math exactly.
// eye computed in double then cast (matches np double -> jnp.float32),
// everything after in fp32 (matches jnp ops).
// ---------------------------------------------------------------------------
static Cam make_cam()
{
    const double PI = 3.14159265358979323846;
    double e = 0.0 * PI / 180.0;          // ELEV
    double a = 90.0 * PI / 180.0;         // AZIM
    const double CD = 2.732;
    float ex = (float)(CD * cos(e) * sin(a));
    float ey = (float)(CD * sin(e));
    float ez = (float)(-CD * cos(e) * cos(a));

    // z = (at - eye)/|.|, at = 0
    float zx = -ex, zy = -ey, zz = -ez;
    float zn = sqrtf(zx*zx + zy*zy + zz*zz);
    zx /= zn; zy /= zn; zz /= zn;
    // x = cross(up, z), up = (0,1,0) -> (zz, 0, -zx)
    float xx = zz, xy = 0.0f, xz = -zx;
    float xn = sqrtf(xx*xx + xy*xy + xz*xz);
    xx /= xn; xy /= xn; xz /= xn;
    // y = cross(z, x)
    float yx = zy*xz - zz*xy;
    float yy = zz*xx - zx*xz;
    float yz = zx*xy - zy*xx;
    float yn = sqrtf(yx*yx + yy*yy + yz*yz);
    yx /= yn; yy /= yn; yz /= yn;

    Cam cam;
    cam.ex = ex; cam.ey = ey; cam.ez = ez;
    cam.r00 = xx; cam.r01 = xy; cam.r02 = xz;
    cam.r10 = yx; cam.r11 = yy; cam.r12 = yz;
    cam.r20 = zx; cam.r21 = zy; cam.r22 = zz;
    cam.width = (float)tan(30.0 * PI / 180.0);
    return cam;
}

extern "C" void kernel_launch(void* const* d_in, const int* in_sizes, int n_in,
                              void* d_out, int out_size)
{
    const float* verts = (const float*)d_in[0];   // (1,512,3) f32
    const float* ref   = (const float*)d_in[1];   // (1,256,256) f32
    const int*   faces = (const int*)  d_in[2];   // (1,1024,3) i32
    float* out = (float*)d_out;

    Cam cam = make_cam();
    prep_kernel<<<1, 1024>>>(verts, faces, cam);
    raster_kernel<<<256, 256>>>(ref);
    final_reduce<<<1, 256>>>(out);
}

// round 2
// speedup vs baseline: 2.3758x; 2.3758x over previous
#include <cuda_runtime.h>
#include <math.h>

#define ISZ 256
#define NV  512
#define NF  1024
#define NEARP 0.1f
#define FARP  100.0f
#define K2A  64          // phase-2a per-pixel candidate cap

__device__ float    g_partial[256];
__device__ unsigned g_ctr = 0;

struct Cam {
    float ex, ey, ez;
    float r00, r01, r02, r10, r11, r12, r20, r21, r22;
    float width;
};

// Test one compacted candidate face against pixel (xs, ys).
__device__ __forceinline__ bool test_face(
    const float4* __restrict__ s_bb, const float4* __restrict__ s_e0,
    const float4* __restrict__ s_e1, const float*  __restrict__ s_rz2,
    int j, float xs, float ys)
{
    float4 bb = s_bb[j];
    if (xs < bb.x || xs > bb.y || ys < bb.z || ys > bb.w) return false;
    float4 e0 = s_e0[j];
    float dx = xs - e0.x, dy = ys - e0.y;
    float w0 = e0.z * dx + e0.w * dy;
    if (!(w0 > 0.0f)) return false;
    float4 e1 = s_e1[j];
    float w1 = e1.x * dx + e1.y * dy;
    float w2 = 1.0f - w0 - w1;
    if (!(w1 > 0.0f) || !(w2 > 0.0f)) return false;
    float inv_z = w0 * e1.z + w1 * e1.w + w2 * s_rz2[j];
    float zp = 1.0f / inv_z;
    return (zp > NEARP) && (zp < FARP);
}

__global__ __launch_bounds__(256) void fused_kernel(
    const float* __restrict__ verts,
    const int*   __restrict__ faces,
    const float* __restrict__ ref,
    float* __restrict__ out,
    Cam cam)
{
    extern __shared__ char sm[];
    float4* s_bb  = (float4*)sm;                         // 1024 * 16
    float4* s_e0  = (float4*)(sm + 16384);               // 1024 * 16
    float4* s_e1  = (float4*)(sm + 32768);               // 1024 * 16
    float*  s_rz2 = (float*) (sm + 49152);               // 1024 * 4
    float*  sxv   = (float*) (sm + 53248);               // 512 * 4
    float*  syv   = (float*) (sm + 55296);
    float*  szv   = (float*) (sm + 57344);
    float*  s_red = (float*) (sm + 59392);               // 256 * 4
    unsigned short* s_upix = (unsigned short*)(sm + 60416); // 256 * 2

    __shared__ int s_cnt, s_ucnt, s_last;

    int t = threadIdx.x;
    if (t == 0) { s_cnt = 0; s_ucnt = 0; s_last = 0; }

    // ---- Vertex transform (redundant per block, 2 verts/thread) ----
    #pragma unroll
    for (int v = t; v < NV; v += 256) {
        float vx = verts[3*v+0] - cam.ex;
        float vy = verts[3*v+1] - cam.ey;
        float vz = verts[3*v+2] - cam.ez;
        float cx = vx*cam.r00 + vy*cam.r01 + vz*cam.r02;
        float cy = vx*cam.r10 + vy*cam.r11 + vz*cam.r12;
        float cz = vx*cam.r20 + vy*cam.r21 + vz*cam.r22;
        float zw = cz * cam.width;
        sxv[v] = cx / zw;
        syv[v] = cy / zw;
        szv[v] = cz;
    }
    __syncthreads();

    // ---- Tile bounds ----
    int tx = blockIdx.x & 15;
    int ty = blockIdx.x >> 4;
    float txmin = (2.0f * (16*tx)        + 1.0f - 256.0f) * (1.0f/256.0f);
    float txmax = (2.0f * (16*tx + 15)   + 1.0f - 256.0f) * (1.0f/256.0f);
    float tymax = (2.0f * (255 - 16*ty)        + 1.0f - 256.0f) * (1.0f/256.0f);
    float tymin = (2.0f * (255 - (16*ty + 15)) + 1.0f - 256.0f) * (1.0f/256.0f);

    // ---- Cull + prep compacted candidate faces (4 faces/thread) ----
    #pragma unroll
    for (int f = t; f < NF; f += 256) {
        int i0 = faces[3*f+0], i1 = faces[3*f+1], i2 = faces[3*f+2];
        float x0 = sxv[i0], x1 = sxv[i1], x2 = sxv[i2];
        float y0 = syv[i0], y1 = syv[i1], y2 = syv[i2];

        float denom = (y1 - y2) * (x0 - x2) + (x2 - x1) * (y0 - y2);
        bool  valid = fabsf(denom) > 1e-9f;

        float bxmin = fminf(x0, fminf(x1, x2));
        float bxmax = fmaxf(x0, fmaxf(x1, x2));
        float bymin = fminf(y0, fminf(y1, y2));
        float bymax = fmaxf(y0, fmaxf(y1, y2));

        if (valid && bxmin <= txmax && bxmax >= txmin &&
                     bymin <= tymax && bymax >= tymin) {
            float rd = 1.0f / denom;
            float z0 = szv[i0], z1 = szv[i1], z2 = szv[i2];
            int pos = atomicAdd(&s_cnt, 1);
            s_bb[pos]  = make_float4(bxmin, bxmax, bymin, bymax);
            s_e0[pos]  = make_float4(x2, y2, (y1 - y2) * rd, (x2 - x1) * rd);
            s_e1[pos]  = make_float4((y2 - y0) * rd, (x0 - x2) * rd,
                                     1.0f / z0, 1.0f / z1);
            s_rz2[pos] = 1.0f / z2;
        }
    }
    __syncthreads();
    int n = s_cnt;

    // ---- Phase 2a: per-pixel scan of first K2A candidates ----
    int c = 16*tx + (t & 15);
    int r = 16*ty + (t >> 4);
    float xs = (2.0f * c + 1.0f - 256.0f) * (1.0f/256.0f);
    float ys = (2.0f * (255 - r) + 1.0f - 256.0f) * (1.0f/256.0f);

    bool covered = false;
    int kcap = (n < K2A) ? n : K2A;
    for (int j = 0; j < kcap; j++) {
        if (test_face(s_bb, s_e0, s_e1, s_rz2, j, xs, ys)) { covered = true; break; }
    }
    if (!covered && n > K2A) {
        int pos = atomicAdd(&s_ucnt, 1);
        s_upix[pos] = (unsigned short)t;
    }
    s_red[t] = covered ? 1.0f : 0.0f;
    __syncthreads();

    // ---- Phase 2b: warp-cooperative scan for remaining pixels ----
    int m    = s_ucnt;
    int warp = t >> 5, lane = t & 31;
    for (int i = warp; i < m; i += 8) {
        int p  = s_upix[i];
        int pc = 16*tx + (p & 15);
        int pr = 16*ty + (p >> 4);
        float pxs = (2.0f * pc + 1.0f - 256.0f) * (1.0f/256.0f);
        float pys = (2.0f * (255 - pr) + 1.0f - 256.0f) * (1.0f/256.0f);
        bool any = false;
        for (int j0 = K2A; j0 < n; j0 += 32) {
            int j = j0 + lane;
            bool hit = (j < n) && test_face(s_bb, s_e0, s_e1, s_rz2, j, pxs, pys);
            if (__ballot_sync(0xffffffffu, hit)) { any = true; break; }
        }
        if (lane == 0) s_red[p] = any ? 1.0f : 0.0f;
    }
    __syncthreads();

    // ---- Phase 3: loss + fixed-order block reduction ----
    float d = s_red[t] - ref[r * ISZ + c];
    __syncthreads();
    s_red[t] = d * d;
    __syncthreads();
    #pragma unroll
    for (int off = 128; off > 0; off >>= 1) {
        if (t < off) s_red[t] += s_red[t + off];
        __syncthreads();
    }
    if (t == 0) g_partial[blockIdx.x] = s_red[0];

    // ---- Last-block deterministic final reduce ----
    if (t == 0) {
        __threadfence();
        unsigned rank = atomicInc(&g_ctr, 255u);  // wraps to 0 -> graph-replay safe
        s_last = (rank == 255u);
    }
    __syncthreads();
    if (s_last) {
        volatile float* gp = g_partial;
        s_red[t] = gp[t];
        __syncthreads();
        #pragma unroll
        for (int off = 128; off > 0; off >>= 1) {
            if (t < off) s_red[t] += s_red[t + off];
            __syncthreads();
        }
        if (t == 0) out[0] = s_red[0];
    }
}

// ---------------------------------------------------------------------------
// Host: camera constants mirroring the reference fp32 math.
// ---------------------------------------------------------------------------
static Cam make_cam()
{
    const double PI = 3.14159265358979323846;
    double e = 0.0 * PI / 180.0;
    double a = 90.0 * PI / 180.0;
    const double CD = 2.732;
    float ex = (float)(CD * cos(e) * sin(a));
    float ey = (float)(CD * sin(e));
    float ez = (float)(-CD * cos(e) * cos(a));

    float zx = -ex, zy = -ey, zz = -ez;
    float zn = sqrtf(zx*zx + zy*zy + zz*zz);
    zx /= zn; zy /= zn; zz /= zn;
    float xx = zz, xy = 0.0f, xz = -zx;
    float xn = sqrtf(xx*xx + xy*xy + xz*xz);
    xx /= xn; xy /= xn; xz /= xn;
    float yx = zy*xz - zz*xy;
    float yy = zz*xx - zx*xz;
    float yz = zx*xy - zy*xx;
    float yn = sqrtf(yx*yx + yy*yy + yz*yz);
    yx /= yn; yy /= yn; yz /= yn;

    Cam cam;
    cam.ex = ex; cam.ey = ey; cam.ez = ez;
    cam.r00 = xx; cam.r01 = xy; cam.r02 = xz;
    cam.r10 = yx; cam.r11 = yy; cam.r12 = yz;
    cam.r20 = zx; cam.r21 = zy; cam.r22 = zz;
    cam.width = (float)tan(30.0 * PI / 180.0);
    return cam;
}

extern "C" void kernel_launch(void* const* d_in, const int* in_sizes, int n_in,
                              void* d_out, int out_size)
{
    const float* verts = (const float*)d_in[0];   // (1,512,3) f32
    const float* ref   = (const float*)d_in[1];   // (1,256,256) f32
    const int*   faces = (const int*)  d_in[2];   // (1,1024,3) i32
    float* out = (float*)d_out;

    static bool attr_set = false;
    if (!attr_set) {
        cudaFuncSetAttribute(fused_kernel,
                             cudaFuncAttributeMaxDynamicSharedMemorySize, 65536);
        attr_set = true;
    }

    Cam cam = make_cam();
    fused_kernel<<<256, 256, 61440>>>(verts, faces, ref, out, cam);
}